// round 8
// baseline (speedup 1.0000x reference)
#include <cuda_runtime.h>
#include <cuda_bf16.h>
#include <cuda_fp16.h>

#define NN 50000
#define NG 1000
#define HID 64
#define NE_MAX 1600000
#define KW 2048
#define KPAD 72
#define APAD 72
#define NB 49

typedef unsigned long long u64;
typedef unsigned int u32;

// ---------------- scratch ----------------------------------------------------
__device__ __half g_t[NN * HID];     // layer-1 pre-aggregation features (fp16)
__device__ __half g_hs[NN * HID];    // relu(...)*ns features (fp16)
__device__ float g_z[NN * HID];      // layer-2 aggregated (fp32, feeds 2-term split)
__device__ int g_deg_in[NN];
__device__ int g_deg_out[NN];
__device__ int g_off[NN + 1];
__device__ int g_offtmp[NN];
__device__ int g_ctr[NN];
__device__ int g_bsum[NB];
__device__ int g_bpre[NB];
__device__ int g_csr[NE_MAX];
__device__ float g_norm_src[NN];
__device__ float g_norm_dst[NN];
__device__ __half g_W0h[HID * KW];
__device__ __half g_Bb[1024 * HID];
__device__ __half g_Bg[1024 * HID];

// ---------------- helpers -----------------------------------------------------
__device__ __forceinline__ u32 smem_u32(const void* p) {
    u32 a;
    asm("{ .reg .u64 t; cvta.to.shared.u64 t, %1; cvt.u32.u64 %0, t; }" : "=r"(a) : "l"(p));
    return a;
}
__device__ __forceinline__ void mma_f16(float* d, u32 a0, u32 a1, u32 a2, u32 a3,
                                        u32 b0, u32 b1) {
    asm volatile(
        "mma.sync.aligned.m16n8k16.row.col.f32.f16.f16.f32 "
        "{%0,%1,%2,%3}, {%4,%5,%6,%7}, {%8,%9}, {%0,%1,%2,%3};"
        : "+f"(d[0]), "+f"(d[1]), "+f"(d[2]), "+f"(d[3])
        : "r"(a0), "r"(a1), "r"(a2), "r"(a3), "r"(b0), "r"(b1));
}
__device__ __forceinline__ void cvt_h2(float a, float b, u32& hi, u32& lo) {
    __half2 h = __floats2half2_rn(a, b);
    float ra = a - __half2float(__low2half(h));
    float rb = b - __half2float(__high2half(h));
    __half2 l = __floats2half2_rn(ra, rb);
    hi = *(u32*)&h; lo = *(u32*)&l;
}
__device__ __forceinline__ void cp16(u32 daddr, const void* gp, int zf) {
    asm volatile("cp.async.ca.shared.global [%0], [%1], 16, %2;"
                 :: "r"(daddr), "l"(gp), "r"(zf));
}
__device__ __forceinline__ void cp16f(u32 daddr, const void* gp) {
    asm volatile("cp.async.ca.shared.global [%0], [%1], 16;"
                 :: "r"(daddr), "l"(gp));
}

// ---------------- weight pre-conversion ---------------------------------------
__global__ void k_prep(const float* __restrict__ W0, const float* __restrict__ W1) {
    int idx = blockIdx.x * blockDim.x + threadIdx.x;
    if (idx < HID * KW) {
        int n = idx / KW, k = idx % KW;
        float w = (k < 2 * NG) ? W0[k * HID + n] : 0.f;
        g_W0h[idx] = __float2half(w);
    }
    if (idx < 1024 * HID) {
        int g = idx / HID, k = idx % HID;
        float wb = (g < NG) ? W1[k * 2 * NG + g] : 0.f;
        float wg = (g < NG) ? W1[k * 2 * NG + NG + g] : 0.f;
        g_Bb[idx] = __float2half(wb);
        g_Bg[idx] = __float2half(wg);
    }
}

// ---------------- degree count -------------------------------------------------
__global__ void k_count(const int* __restrict__ src, const int* __restrict__ dst, int E) {
    int e4 = (blockIdx.x * blockDim.x + threadIdx.x) * 4;
    if (e4 + 3 < E) {
        int4 s = *(const int4*)&src[e4];
        int4 d = *(const int4*)&dst[e4];
        atomicAdd(&g_deg_out[s.x], 1); atomicAdd(&g_deg_out[s.y], 1);
        atomicAdd(&g_deg_out[s.z], 1); atomicAdd(&g_deg_out[s.w], 1);
        atomicAdd(&g_deg_in[d.x], 1);  atomicAdd(&g_deg_in[d.y], 1);
        atomicAdd(&g_deg_in[d.z], 1);  atomicAdd(&g_deg_in[d.w], 1);
    } else {
        for (int e = e4; e < E; e++) {
            atomicAdd(&g_deg_out[src[e]], 1);
            atomicAdd(&g_deg_in[dst[e]], 1);
        }
    }
}

// ---------------- scan ----------------------------------------------------------
__global__ __launch_bounds__(1024) void k_scan1() {
    __shared__ int s[1024];
    int t = threadIdx.x;
    int i = blockIdx.x * 1024 + t;
    int v = (i < NN) ? g_deg_in[i] : 0;
    s[t] = v;
    __syncthreads();
    #pragma unroll
    for (int d = 1; d < 1024; d <<= 1) {
        int x = (t >= d) ? s[t - d] : 0;
        __syncthreads();
        s[t] += x;
        __syncthreads();
    }
    if (i < NN) g_offtmp[i] = s[t];
    if (t == 1023) g_bsum[blockIdx.x] = s[1023];
}

__global__ void k_scan2() {
    __shared__ int s[64];
    int t = threadIdx.x;
    int v = (t < NB) ? g_bsum[t] : 0;
    s[t] = v;
    __syncthreads();
    #pragma unroll
    for (int d = 1; d < 64; d <<= 1) {
        int x = (t >= d) ? s[t - d] : 0;
        __syncthreads();
        s[t] += x;
        __syncthreads();
    }
    if (t < NB) g_bpre[t] = s[t] - v;
}

__global__ __launch_bounds__(1024) void k_scan3() {
    int i = blockIdx.x * 1024 + threadIdx.x;
    if (i >= NN) return;
    int v = g_deg_in[i];
    int excl = g_offtmp[i] - v + g_bpre[blockIdx.x];
    g_off[i] = excl;
    if (i == NN - 1) g_off[NN] = excl + v;
    g_norm_dst[i] = rsqrtf(fmaxf((float)v, 1.0f));
    g_norm_src[i] = rsqrtf(fmaxf((float)g_deg_out[i], 1.0f));
}

// ---------------- CSR fill -------------------------------------------------------
__global__ void k_fill(const int* __restrict__ src, const int* __restrict__ dst, int E) {
    int e4 = (blockIdx.x * blockDim.x + threadIdx.x) * 4;
    if (e4 + 3 < E) {
        int4 s = *(const int4*)&src[e4];
        int4 d = *(const int4*)&dst[e4];
        g_csr[g_off[d.x] + atomicAdd(&g_ctr[d.x], 1)] = s.x;
        g_csr[g_off[d.y] + atomicAdd(&g_ctr[d.y], 1)] = s.y;
        g_csr[g_off[d.z] + atomicAdd(&g_ctr[d.z], 1)] = s.z;
        g_csr[g_off[d.w] + atomicAdd(&g_ctr[d.w], 1)] = s.w;
    } else {
        for (int e = e4; e < E; e++) {
            int d = dst[e];
            g_csr[g_off[d] + atomicAdd(&g_ctr[d], 1)] = src[e];
        }
    }
}

// ---------------- GEMM1: g_t = concat(xu,xs) @ W0 (unscaled, fp16 out) ----------
#define G1_SMEM (2 * 128 * APAD * 4 + 2 * 64 * KPAD * 2)
__global__ __launch_bounds__(256, 2) void k_gemm1(
    const float* __restrict__ xu, const float* __restrict__ xs) {
    extern __shared__ __align__(16) char sm[];
    float* Af = (float*)sm;
    __half* Bsm = (__half*)(sm + 2 * 128 * APAD * 4);
    u32 aBase = smem_u32(sm);
    u32 bBase = aBase + 2 * 128 * APAD * 4;

    int tid = threadIdx.x, warp = tid >> 5, lane = tid & 31;
    int grp = lane >> 2, tig = lane & 3;
    int i0 = blockIdx.x * 128, m0 = warp * 16;

    float acc[8][4];
    #pragma unroll
    for (int n = 0; n < 8; n++)
        #pragma unroll
        for (int j = 0; j < 4; j++) acc[n][j] = 0.f;

    auto loadA = [&](int c) {
        int kb = c * 64;
        u32 da = aBase + (u32)(c & 1) * 128 * APAD * 4;
        #pragma unroll
        for (int q = 0; q < 8; q++) {
            int idx = q * 256 + tid;
            int r = idx >> 4, kq = (idx & 15) << 2;
            int i = i0 + r, k = kb + kq;
            const float* gp = xu;
            int zf = 0;
            if (i < NN && k < 2 * NG) {
                gp = (k < NG) ? xu + (size_t)i * NG + k
                              : xs + (size_t)i * NG + (k - NG);
                zf = 16;
            }
            cp16(da + (r * APAD + kq) * 4, gp, zf);
        }
        u32 db = bBase + (u32)(c & 1) * (64 * KPAD * 2);
        #pragma unroll
        for (int q = 0; q < 2; q++) {
            int idx = q * 256 + tid;
            int n = idx >> 3, kq = (idx & 7) << 3;
            cp16f(db + (n * KPAD + kq) * 2, g_W0h + n * KW + kb + kq);
        }
        asm volatile("cp.async.commit_group;" ::: "memory");
    };

    loadA(0);
    for (int c = 0; c < 32; c++) {
        if (c < 31) {
            loadA(c + 1);
            asm volatile("cp.async.wait_group 1;" ::: "memory");
        } else {
            asm volatile("cp.async.wait_group 0;" ::: "memory");
        }
        __syncthreads();

        const float* A = Af + (c & 1) * 128 * APAD;
        const __half* Bh = Bsm + (c & 1) * 64 * KPAD;

        #pragma unroll
        for (int ks = 0; ks < 4; ks++) {
            int k0 = ks * 16;
            float2 f0 = *(const float2*)&A[(m0 + grp) * APAD + k0 + 2 * tig];
            float2 f1 = *(const float2*)&A[(m0 + grp + 8) * APAD + k0 + 2 * tig];
            float2 f2 = *(const float2*)&A[(m0 + grp) * APAD + k0 + 2 * tig + 8];
            float2 f3 = *(const float2*)&A[(m0 + grp + 8) * APAD + k0 + 2 * tig + 8];
            u32 ah0, al0, ah1, al1, ah2, al2, ah3, al3;
            cvt_h2(f0.x, f0.y, ah0, al0);
            cvt_h2(f1.x, f1.y, ah1, al1);
            cvt_h2(f2.x, f2.y, ah2, al2);
            cvt_h2(f3.x, f3.y, ah3, al3);
            #pragma unroll
            for (int n = 0; n < 8; n++) {
                int nb = n * 8 + grp;
                u32 bh0 = *(const u32*)&Bh[nb * KPAD + k0 + 2 * tig];
                u32 bh1 = *(const u32*)&Bh[nb * KPAD + k0 + 2 * tig + 8];
                mma_f16(acc[n], ah0, ah1, ah2, ah3, bh0, bh1);
                mma_f16(acc[n], al0, al1, al2, al3, bh0, bh1);
            }
        }
        __syncthreads();
    }

    int r0 = i0 + m0 + grp;
    int r1 = r0 + 8;
    #pragma unroll
    for (int n = 0; n < 8; n++) {
        int col = n * 8 + tig * 2;
        if (r0 < NN)
            *(__half2*)&g_t[(size_t)r0 * HID + col] = __floats2half2_rn(acc[n][0], acc[n][1]);
        if (r1 < NN)
            *(__half2*)&g_t[(size_t)r1 * HID + col] = __floats2half2_rn(acc[n][2], acc[n][3]);
    }
}

// ---------------- CSR gather: warp per node, fp16 rows ---------------------------
// MODE 0: per-edge *norm_src[s]; out(half) = relu(sum*nd + b0)*ns
// MODE 1: plain sum;              out(float) = sum*nd
template <int MODE>
__global__ __launch_bounds__(256) void k_gather(const __half* __restrict__ t,
                                                const float* __restrict__ b0,
                                                void* __restrict__ optr) {
    int gw = (blockIdx.x * 256 + threadIdx.x) >> 5;
    if (gw >= NN) return;
    int lane = threadIdx.x & 31;
    int beg = g_off[gw], end = g_off[gw + 1];

    float2 acc = make_float2(0.f, 0.f);
    int j = beg;
    for (; j + 4 <= end; j += 4) {
        int s0 = g_csr[j], s1 = g_csr[j + 1], s2 = g_csr[j + 2], s3 = g_csr[j + 3];
        float2 v0 = __half22float2(*(const __half2*)&t[(size_t)s0 * HID + 2 * lane]);
        float2 v1 = __half22float2(*(const __half2*)&t[(size_t)s1 * HID + 2 * lane]);
        float2 v2 = __half22float2(*(const __half2*)&t[(size_t)s2 * HID + 2 * lane]);
        float2 v3 = __half22float2(*(const __half2*)&t[(size_t)s3 * HID + 2 * lane]);
        if (MODE == 0) {
            float n0 = g_norm_src[s0], n1 = g_norm_src[s1];
            float n2 = g_norm_src[s2], n3 = g_norm_src[s3];
            acc.x = fmaf(v0.x, n0, fmaf(v1.x, n1, fmaf(v2.x, n2, fmaf(v3.x, n3, acc.x))));
            acc.y = fmaf(v0.y, n0, fmaf(v1.y, n1, fmaf(v2.y, n2, fmaf(v3.y, n3, acc.y))));
        } else {
            acc.x += v0.x + v1.x + v2.x + v3.x;
            acc.y += v0.y + v1.y + v2.y + v3.y;
        }
    }
    for (; j < end; j++) {
        int s = g_csr[j];
        float2 v = __half22float2(*(const __half2*)&t[(size_t)s * HID + 2 * lane]);
        if (MODE == 0) {
            float ns = g_norm_src[s];
            acc.x = fmaf(v.x, ns, acc.x);
            acc.y = fmaf(v.y, ns, acc.y);
        } else {
            acc.x += v.x; acc.y += v.y;
        }
    }

    float nd = g_norm_dst[gw];
    if (MODE == 0) {
        float ns = g_norm_src[gw];
        float2 b = *(const float2*)&b0[2 * lane];
        float rx = fmaxf(fmaf(acc.x, nd, b.x), 0.f) * ns;
        float ry = fmaxf(fmaf(acc.y, nd, b.y), 0.f) * ns;
        *(__half2*)&((__half*)optr)[(size_t)gw * HID + 2 * lane] = __floats2half2_rn(rx, ry);
    } else {
        float2 r = make_float2(acc.x * nd, acc.y * nd);
        *(float2*)&((float*)optr)[(size_t)gw * HID + 2 * lane] = r;
    }
}

// ---------------- fused GEMM2 + epilogue ------------------------------------------
#define KO_SMEM (128 * APAD * 4 + 2 * 64 * KPAD * 2)
__global__ __launch_bounds__(256) void k_out(
    const float* __restrict__ xu, const float* __restrict__ xs,
    const float* __restrict__ b1, float* __restrict__ out) {
    extern __shared__ __align__(16) char sm[];
    float* Zf = (float*)sm;
    __half* Bsm = (__half*)(sm + 128 * APAD * 4);
    u32 zBase = smem_u32(sm);
    u32 bBase = zBase + 128 * APAD * 4;

    int tid = threadIdx.x, warp = tid >> 5, lane = tid & 31;
    int grp = lane >> 2, tig = lane & 3;
    int i0 = blockIdx.y * 128;
    int g0 = blockIdx.x * 64;
    int m0 = warp * 16;

    #pragma unroll
    for (int q = 0; q < 8; q++) {
        int idx = q * 256 + tid;
        int r = idx >> 4, kq = (idx & 15) << 2;
        int i = i0 + r;
        const float* gp = g_z;
        int zf = 0;
        if (i < NN) { gp = g_z + (size_t)i * HID + kq; zf = 16; }
        cp16(zBase + (r * APAD + kq) * 4, gp, zf);
    }
    #pragma unroll
    for (int q = 0; q < 4; q++) {
        int idx = q * 256 + tid;
        int arr = idx >> 9;
        int rem = idx & 511;
        int n = rem >> 3, kq = (rem & 7) << 3;
        const __half* base = arr ? g_Bg : g_Bb;
        cp16f(bBase + arr * (64 * KPAD * 2) + (n * KPAD + kq) * 2,
              base + (g0 + n) * HID + kq);
    }
    asm volatile("cp.async.commit_group;" ::: "memory");
    asm volatile("cp.async.wait_group 0;" ::: "memory");
    __syncthreads();

    const __half* Bb = Bsm;
    const __half* Bg = Bsm + 64 * KPAD;

    float aB[8][4], aG[8][4];
    #pragma unroll
    for (int n = 0; n < 8; n++)
        #pragma unroll
        for (int j = 0; j < 4; j++) { aB[n][j] = 0.f; aG[n][j] = 0.f; }

    #pragma unroll
    for (int ks = 0; ks < 4; ks++) {
        int k0 = ks * 16;
        float2 f0 = *(const float2*)&Zf[(m0 + grp) * APAD + k0 + 2 * tig];
        float2 f1 = *(const float2*)&Zf[(m0 + grp + 8) * APAD + k0 + 2 * tig];
        float2 f2 = *(const float2*)&Zf[(m0 + grp) * APAD + k0 + 2 * tig + 8];
        float2 f3 = *(const float2*)&Zf[(m0 + grp + 8) * APAD + k0 + 2 * tig + 8];
        u32 ah0, al0, ah1, al1, ah2, al2, ah3, al3;
        cvt_h2(f0.x, f0.y, ah0, al0);
        cvt_h2(f1.x, f1.y, ah1, al1);
        cvt_h2(f2.x, f2.y, ah2, al2);
        cvt_h2(f3.x, f3.y, ah3, al3);
        #pragma unroll
        for (int n = 0; n < 8; n++) {
            int nb = n * 8 + grp;
            u32 b0r = *(const u32*)&Bb[nb * KPAD + k0 + 2 * tig];
            u32 b1r = *(const u32*)&Bb[nb * KPAD + k0 + 2 * tig + 8];
            mma_f16(aB[n], ah0, ah1, ah2, ah3, b0r, b1r);
            mma_f16(aB[n], al0, al1, al2, al3, b0r, b1r);
            u32 g0r = *(const u32*)&Bg[nb * KPAD + k0 + 2 * tig];
            u32 g1r = *(const u32*)&Bg[nb * KPAD + k0 + 2 * tig + 8];
            mma_f16(aG[n], ah0, ah1, ah2, ah3, g0r, g1r);
            mma_f16(aG[n], al0, al1, al2, al3, g0r, g1r);
        }
    }

    int r0 = i0 + m0 + grp;
    int r1 = r0 + 8;
    #pragma unroll
    for (int n = 0; n < 8; n++) {
        int gene = g0 + n * 8 + tig * 2;
        if (gene >= NG) continue;
        float2 bb = *(const float2*)&b1[gene];
        float2 bg = *(const float2*)&b1[NG + gene];
        if (r0 < NN) {
            float2 u = *(const float2*)&xu[(size_t)r0 * NG + gene];
            float2 s = *(const float2*)&xs[(size_t)r0 * NG + gene];
            float2 o;
            o.x = (aB[n][0] + bb.x) * u.x + (aG[n][0] + bg.x) * s.x;
            o.y = (aB[n][1] + bb.y) * u.y + (aG[n][1] + bg.y) * s.y;
            *(float2*)&out[(size_t)r0 * NG + gene] = o;
        }
        if (r1 < NN) {
            float2 u = *(const float2*)&xu[(size_t)r1 * NG + gene];
            float2 s = *(const float2*)&xs[(size_t)r1 * NG + gene];
            float2 o;
            o.x = (aB[n][2] + bb.x) * u.x + (aG[n][2] + bg.x) * s.x;
            o.y = (aB[n][3] + bb.y) * u.y + (aG[n][3] + bg.y) * s.y;
            *(float2*)&out[(size_t)r1 * NG + gene] = o;
        }
    }
}

// ---------------- host launcher ---------------------------------------------------
extern "C" void kernel_launch(void* const* d_in, const int* in_sizes, int n_in,
                              void* d_out, int out_size) {
    const float* xu = (const float*)d_in[0];
    const float* xs = (const float*)d_in[1];
    const float* W0 = (const float*)d_in[2];
    const float* b0 = (const float*)d_in[3];
    const float* W1 = (const float*)d_in[4];
    const float* b1 = (const float*)d_in[5];
    const int* src = (const int*)d_in[6];
    const int* dst = (const int*)d_in[7];
    int E = in_sizes[6];
    float* out = (float*)d_out;

    void *p_degi, *p_dego, *p_ctr, *p_t, *p_hs, *p_z;
    cudaGetSymbolAddress(&p_degi, g_deg_in);
    cudaGetSymbolAddress(&p_dego, g_deg_out);
    cudaGetSymbolAddress(&p_ctr, g_ctr);
    cudaGetSymbolAddress(&p_t, g_t);
    cudaGetSymbolAddress(&p_hs, g_hs);
    cudaGetSymbolAddress(&p_z, g_z);

    static cudaStream_t s1 = nullptr;
    static cudaEvent_t evFork = nullptr, evJoin = nullptr;
    static int attr_done = 0;
    if (!attr_done) {
        cudaFuncSetAttribute(k_gemm1, cudaFuncAttributeMaxDynamicSharedMemorySize, G1_SMEM);
        cudaFuncSetAttribute(k_out, cudaFuncAttributeMaxDynamicSharedMemorySize, KO_SMEM);
        cudaStreamCreateWithFlags(&s1, cudaStreamNonBlocking);
        cudaEventCreateWithFlags(&evFork, cudaEventDisableTiming);
        cudaEventCreateWithFlags(&evJoin, cudaEventDisableTiming);
        attr_done = 1;
    }

    cudaEventRecord(evFork, 0);
    cudaStreamWaitEvent(s1, evFork, 0);

    // chain B: CSR build
    cudaMemsetAsync(p_degi, 0, NN * sizeof(int), s1);
    cudaMemsetAsync(p_dego, 0, NN * sizeof(int), s1);
    cudaMemsetAsync(p_ctr, 0, NN * sizeof(int), s1);
    k_count<<<(E / 4 + 255) / 256, 256, 0, s1>>>(src, dst, E);
    k_scan1<<<NB, 1024, 0, s1>>>();
    k_scan2<<<1, 64, 0, s1>>>();
    k_scan3<<<NB, 1024, 0, s1>>>();
    k_fill<<<(E / 4 + 255) / 256, 256, 0, s1>>>(src, dst, E);
    cudaEventRecord(evJoin, s1);

    // chain A: weights + GEMM1
    k_prep<<<(HID * KW + 255) / 256, 256>>>(W0, W1);
    k_gemm1<<<(NN + 127) / 128, 256, G1_SMEM>>>(xu, xs);

    cudaStreamWaitEvent(0, evJoin, 0);

    k_gather<0><<<(NN * 32 + 255) / 256, 256>>>((const __half*)p_t, b0, p_hs);
    k_gather<1><<<(NN * 32 + 255) / 256, 256>>>((const __half*)p_hs, b0, p_z);
    k_out<<<dim3(16, (NN + 127) / 128), 256, KO_SMEM>>>(xu, xs, b1, out);
}

// round 9
// speedup vs baseline: 1.0485x; 1.0485x over previous
#include <cuda_runtime.h>
#include <cuda_bf16.h>
#include <cuda_fp16.h>

#define NN 50000
#define NG 1000
#define HID 64
#define NE_MAX 1600000
#define KW 2048
#define KPAD 72
#define APAD 72
#define NB 49

typedef unsigned long long u64;
typedef unsigned int u32;

// ---------------- scratch ----------------------------------------------------
__device__ __half g_t[NN * HID];     // layer-1 pre-aggregation features (fp16)
__device__ __half g_hs[NN * HID];    // relu(...)*ns features (fp16)
__device__ float g_z[NN * HID];      // layer-2 aggregated (fp32)
__device__ int g_deg_in[NN];
__device__ int g_deg_out[NN];
__device__ int g_off[NN + 1];
__device__ int g_offtmp[NN];
__device__ int g_ctr[NN];
__device__ int g_bsum[NB];
__device__ int g_bpre[NB];
__device__ int g_csr[NE_MAX];
__device__ float g_norm_src[NN];
__device__ float g_norm_dst[NN];
__device__ __half g_W0h[HID * KW];
__device__ __half g_Bb[1024 * HID];
__device__ __half g_Bg[1024 * HID];

// ---------------- helpers -----------------------------------------------------
__device__ __forceinline__ u32 smem_u32(const void* p) {
    u32 a;
    asm("{ .reg .u64 t; cvta.to.shared.u64 t, %1; cvt.u32.u64 %0, t; }" : "=r"(a) : "l"(p));
    return a;
}
__device__ __forceinline__ void mma_f16(float* d, u32 a0, u32 a1, u32 a2, u32 a3,
                                        u32 b0, u32 b1) {
    asm volatile(
        "mma.sync.aligned.m16n8k16.row.col.f32.f16.f16.f32 "
        "{%0,%1,%2,%3}, {%4,%5,%6,%7}, {%8,%9}, {%0,%1,%2,%3};"
        : "+f"(d[0]), "+f"(d[1]), "+f"(d[2]), "+f"(d[3])
        : "r"(a0), "r"(a1), "r"(a2), "r"(a3), "r"(b0), "r"(b1));
}
__device__ __forceinline__ u32 pack_h2(float a, float b) {
    __half2 h = __floats2half2_rn(a, b);
    return *(u32*)&h;
}
__device__ __forceinline__ void cp16(u32 daddr, const void* gp, int zf) {
    asm volatile("cp.async.ca.shared.global [%0], [%1], 16, %2;"
                 :: "r"(daddr), "l"(gp), "r"(zf));
}
__device__ __forceinline__ void cp16f(u32 daddr, const void* gp) {
    asm volatile("cp.async.ca.shared.global [%0], [%1], 16;"
                 :: "r"(daddr), "l"(gp));
}

// ---------------- weight pre-conversion ---------------------------------------
__global__ void k_prep(const float* __restrict__ W0, const float* __restrict__ W1) {
    int idx = blockIdx.x * blockDim.x + threadIdx.x;
    if (idx < HID * KW) {
        int n = idx / KW, k = idx % KW;
        float w = (k < 2 * NG) ? W0[k * HID + n] : 0.f;
        g_W0h[idx] = __float2half(w);
    }
    if (idx < 1024 * HID) {
        int g = idx / HID, k = idx % HID;
        float wb = (g < NG) ? W1[k * 2 * NG + g] : 0.f;
        float wg = (g < NG) ? W1[k * 2 * NG + NG + g] : 0.f;
        g_Bb[idx] = __float2half(wb);
        g_Bg[idx] = __float2half(wg);
    }
}

// ---------------- degree count -------------------------------------------------
__global__ void k_count(const int* __restrict__ src, const int* __restrict__ dst, int E) {
    int e4 = (blockIdx.x * blockDim.x + threadIdx.x) * 4;
    if (e4 + 3 < E) {
        int4 s = *(const int4*)&src[e4];
        int4 d = *(const int4*)&dst[e4];
        atomicAdd(&g_deg_out[s.x], 1); atomicAdd(&g_deg_out[s.y], 1);
        atomicAdd(&g_deg_out[s.z], 1); atomicAdd(&g_deg_out[s.w], 1);
        atomicAdd(&g_deg_in[d.x], 1);  atomicAdd(&g_deg_in[d.y], 1);
        atomicAdd(&g_deg_in[d.z], 1);  atomicAdd(&g_deg_in[d.w], 1);
    } else {
        for (int e = e4; e < E; e++) {
            atomicAdd(&g_deg_out[src[e]], 1);
            atomicAdd(&g_deg_in[dst[e]], 1);
        }
    }
}

// ---------------- scan ----------------------------------------------------------
__global__ __launch_bounds__(1024) void k_scan1() {
    __shared__ int s[1024];
    int t = threadIdx.x;
    int i = blockIdx.x * 1024 + t;
    int v = (i < NN) ? g_deg_in[i] : 0;
    s[t] = v;
    __syncthreads();
    #pragma unroll
    for (int d = 1; d < 1024; d <<= 1) {
        int x = (t >= d) ? s[t - d] : 0;
        __syncthreads();
        s[t] += x;
        __syncthreads();
    }
    if (i < NN) g_offtmp[i] = s[t];
    if (t == 1023) g_bsum[blockIdx.x] = s[1023];
}

__global__ void k_scan2() {
    __shared__ int s[64];
    int t = threadIdx.x;
    int v = (t < NB) ? g_bsum[t] : 0;
    s[t] = v;
    __syncthreads();
    #pragma unroll
    for (int d = 1; d < 64; d <<= 1) {
        int x = (t >= d) ? s[t - d] : 0;
        __syncthreads();
        s[t] += x;
        __syncthreads();
    }
    if (t < NB) g_bpre[t] = s[t] - v;
}

__global__ __launch_bounds__(1024) void k_scan3() {
    int i = blockIdx.x * 1024 + threadIdx.x;
    if (i >= NN) return;
    int v = g_deg_in[i];
    int excl = g_offtmp[i] - v + g_bpre[blockIdx.x];
    g_off[i] = excl;
    if (i == NN - 1) g_off[NN] = excl + v;
    g_norm_dst[i] = rsqrtf(fmaxf((float)v, 1.0f));
    g_norm_src[i] = rsqrtf(fmaxf((float)g_deg_out[i], 1.0f));
}

// ---------------- CSR fill -------------------------------------------------------
__global__ void k_fill(const int* __restrict__ src, const int* __restrict__ dst, int E) {
    int e4 = (blockIdx.x * blockDim.x + threadIdx.x) * 4;
    if (e4 + 3 < E) {
        int4 s = *(const int4*)&src[e4];
        int4 d = *(const int4*)&dst[e4];
        g_csr[g_off[d.x] + atomicAdd(&g_ctr[d.x], 1)] = s.x;
        g_csr[g_off[d.y] + atomicAdd(&g_ctr[d.y], 1)] = s.y;
        g_csr[g_off[d.z] + atomicAdd(&g_ctr[d.z], 1)] = s.z;
        g_csr[g_off[d.w] + atomicAdd(&g_ctr[d.w], 1)] = s.w;
    } else {
        for (int e = e4; e < E; e++) {
            int d = dst[e];
            g_csr[g_off[d] + atomicAdd(&g_ctr[d], 1)] = src[e];
        }
    }
}

// ---------------- GEMM1: g_t = concat(xu,xs) @ W0 (1-term fp16) -----------------
#define G1_SMEM (2 * 128 * APAD * 4 + 2 * 64 * KPAD * 2)
__global__ __launch_bounds__(256, 2) void k_gemm1(
    const float* __restrict__ xu, const float* __restrict__ xs) {
    extern __shared__ __align__(16) char sm[];
    float* Af = (float*)sm;
    __half* Bsm = (__half*)(sm + 2 * 128 * APAD * 4);
    u32 aBase = smem_u32(sm);
    u32 bBase = aBase + 2 * 128 * APAD * 4;

    int tid = threadIdx.x, warp = tid >> 5, lane = tid & 31;
    int grp = lane >> 2, tig = lane & 3;
    int i0 = blockIdx.x * 128, m0 = warp * 16;

    float acc[8][4];
    #pragma unroll
    for (int n = 0; n < 8; n++)
        #pragma unroll
        for (int j = 0; j < 4; j++) acc[n][j] = 0.f;

    auto loadA = [&](int c) {
        int kb = c * 64;
        u32 da = aBase + (u32)(c & 1) * 128 * APAD * 4;
        #pragma unroll
        for (int q = 0; q < 8; q++) {
            int idx = q * 256 + tid;
            int r = idx >> 4, kq = (idx & 15) << 2;
            int i = i0 + r, k = kb + kq;
            const float* gp = xu;
            int zf = 0;
            if (i < NN && k < 2 * NG) {
                gp = (k < NG) ? xu + (size_t)i * NG + k
                              : xs + (size_t)i * NG + (k - NG);
                zf = 16;
            }
            cp16(da + (r * APAD + kq) * 4, gp, zf);
        }
        u32 db = bBase + (u32)(c & 1) * (64 * KPAD * 2);
        #pragma unroll
        for (int q = 0; q < 2; q++) {
            int idx = q * 256 + tid;
            int n = idx >> 3, kq = (idx & 7) << 3;
            cp16f(db + (n * KPAD + kq) * 2, g_W0h + n * KW + kb + kq);
        }
        asm volatile("cp.async.commit_group;" ::: "memory");
    };

    loadA(0);
    for (int c = 0; c < 32; c++) {
        if (c < 31) {
            loadA(c + 1);
            asm volatile("cp.async.wait_group 1;" ::: "memory");
        } else {
            asm volatile("cp.async.wait_group 0;" ::: "memory");
        }
        __syncthreads();

        const float* A = Af + (c & 1) * 128 * APAD;
        const __half* Bh = Bsm + (c & 1) * 64 * KPAD;

        #pragma unroll
        for (int ks = 0; ks < 4; ks++) {
            int k0 = ks * 16;
            float2 f0 = *(const float2*)&A[(m0 + grp) * APAD + k0 + 2 * tig];
            float2 f1 = *(const float2*)&A[(m0 + grp + 8) * APAD + k0 + 2 * tig];
            float2 f2 = *(const float2*)&A[(m0 + grp) * APAD + k0 + 2 * tig + 8];
            float2 f3 = *(const float2*)&A[(m0 + grp + 8) * APAD + k0 + 2 * tig + 8];
            u32 ah0 = pack_h2(f0.x, f0.y);
            u32 ah1 = pack_h2(f1.x, f1.y);
            u32 ah2 = pack_h2(f2.x, f2.y);
            u32 ah3 = pack_h2(f3.x, f3.y);
            #pragma unroll
            for (int n = 0; n < 8; n++) {
                int nb = n * 8 + grp;
                u32 bh0 = *(const u32*)&Bh[nb * KPAD + k0 + 2 * tig];
                u32 bh1 = *(const u32*)&Bh[nb * KPAD + k0 + 2 * tig + 8];
                mma_f16(acc[n], ah0, ah1, ah2, ah3, bh0, bh1);
            }
        }
        __syncthreads();
    }

    int r0 = i0 + m0 + grp;
    int r1 = r0 + 8;
    #pragma unroll
    for (int n = 0; n < 8; n++) {
        int col = n * 8 + tig * 2;
        if (r0 < NN)
            *(__half2*)&g_t[(size_t)r0 * HID + col] = __floats2half2_rn(acc[n][0], acc[n][1]);
        if (r1 < NN)
            *(__half2*)&g_t[(size_t)r1 * HID + col] = __floats2half2_rn(acc[n][2], acc[n][3]);
    }
}

// ---------------- CSR gather: warp per node, fp16 rows ---------------------------
template <int MODE>
__global__ __launch_bounds__(256) void k_gather(const __half* __restrict__ t,
                                                const float* __restrict__ b0,
                                                void* __restrict__ optr) {
    int gw = (blockIdx.x * 256 + threadIdx.x) >> 5;
    if (gw >= NN) return;
    int lane = threadIdx.x & 31;
    int beg = g_off[gw], end = g_off[gw + 1];

    float2 acc = make_float2(0.f, 0.f);
    int j = beg;
    for (; j + 4 <= end; j += 4) {
        int s0 = g_csr[j], s1 = g_csr[j + 1], s2 = g_csr[j + 2], s3 = g_csr[j + 3];
        float2 v0 = __half22float2(*(const __half2*)&t[(size_t)s0 * HID + 2 * lane]);
        float2 v1 = __half22float2(*(const __half2*)&t[(size_t)s1 * HID + 2 * lane]);
        float2 v2 = __half22float2(*(const __half2*)&t[(size_t)s2 * HID + 2 * lane]);
        float2 v3 = __half22float2(*(const __half2*)&t[(size_t)s3 * HID + 2 * lane]);
        if (MODE == 0) {
            float n0 = g_norm_src[s0], n1 = g_norm_src[s1];
            float n2 = g_norm_src[s2], n3 = g_norm_src[s3];
            acc.x = fmaf(v0.x, n0, fmaf(v1.x, n1, fmaf(v2.x, n2, fmaf(v3.x, n3, acc.x))));
            acc.y = fmaf(v0.y, n0, fmaf(v1.y, n1, fmaf(v2.y, n2, fmaf(v3.y, n3, acc.y))));
        } else {
            acc.x += v0.x + v1.x + v2.x + v3.x;
            acc.y += v0.y + v1.y + v2.y + v3.y;
        }
    }
    for (; j < end; j++) {
        int s = g_csr[j];
        float2 v = __half22float2(*(const __half2*)&t[(size_t)s * HID + 2 * lane]);
        if (MODE == 0) {
            float ns = g_norm_src[s];
            acc.x = fmaf(v.x, ns, acc.x);
            acc.y = fmaf(v.y, ns, acc.y);
        } else {
            acc.x += v.x; acc.y += v.y;
        }
    }

    float nd = g_norm_dst[gw];
    if (MODE == 0) {
        float ns = g_norm_src[gw];
        float2 b = *(const float2*)&b0[2 * lane];
        float rx = fmaxf(fmaf(acc.x, nd, b.x), 0.f) * ns;
        float ry = fmaxf(fmaf(acc.y, nd, b.y), 0.f) * ns;
        *(__half2*)&((__half*)optr)[(size_t)gw * HID + 2 * lane] = __floats2half2_rn(rx, ry);
    } else {
        float2 r = make_float2(acc.x * nd, acc.y * nd);
        *(float2*)&((float*)optr)[(size_t)gw * HID + 2 * lane] = r;
    }
}

// ---------------- fused GEMM2 + epilogue (1-term fp16) ----------------------------
#define KO_SMEM (128 * APAD * 4 + 2 * 64 * KPAD * 2)
__global__ __launch_bounds__(256) void k_out(
    const float* __restrict__ xu, const float* __restrict__ xs,
    const float* __restrict__ b1, float* __restrict__ out) {
    extern __shared__ __align__(16) char sm[];
    float* Zf = (float*)sm;
    __half* Bsm = (__half*)(sm + 128 * APAD * 4);
    u32 zBase = smem_u32(sm);
    u32 bBase = zBase + 128 * APAD * 4;

    int tid = threadIdx.x, warp = tid >> 5, lane = tid & 31;
    int grp = lane >> 2, tig = lane & 3;
    int i0 = blockIdx.y * 128;
    int g0 = blockIdx.x * 64;
    int m0 = warp * 16;

    #pragma unroll
    for (int q = 0; q < 8; q++) {
        int idx = q * 256 + tid;
        int r = idx >> 4, kq = (idx & 15) << 2;
        int i = i0 + r;
        const float* gp = g_z;
        int zf = 0;
        if (i < NN) { gp = g_z + (size_t)i * HID + kq; zf = 16; }
        cp16(zBase + (r * APAD + kq) * 4, gp, zf);
    }
    #pragma unroll
    for (int q = 0; q < 4; q++) {
        int idx = q * 256 + tid;
        int arr = idx >> 9;
        int rem = idx & 511;
        int n = rem >> 3, kq = (rem & 7) << 3;
        const __half* base = arr ? g_Bg : g_Bb;
        cp16f(bBase + arr * (64 * KPAD * 2) + (n * KPAD + kq) * 2,
              base + (g0 + n) * HID + kq);
    }
    asm volatile("cp.async.commit_group;" ::: "memory");
    asm volatile("cp.async.wait_group 0;" ::: "memory");
    __syncthreads();

    const __half* Bb = Bsm;
    const __half* Bg = Bsm + 64 * KPAD;

    float aB[8][4], aG[8][4];
    #pragma unroll
    for (int n = 0; n < 8; n++)
        #pragma unroll
        for (int j = 0; j < 4; j++) { aB[n][j] = 0.f; aG[n][j] = 0.f; }

    #pragma unroll
    for (int ks = 0; ks < 4; ks++) {
        int k0 = ks * 16;
        float2 f0 = *(const float2*)&Zf[(m0 + grp) * APAD + k0 + 2 * tig];
        float2 f1 = *(const float2*)&Zf[(m0 + grp + 8) * APAD + k0 + 2 * tig];
        float2 f2 = *(const float2*)&Zf[(m0 + grp) * APAD + k0 + 2 * tig + 8];
        float2 f3 = *(const float2*)&Zf[(m0 + grp + 8) * APAD + k0 + 2 * tig + 8];
        u32 ah0 = pack_h2(f0.x, f0.y);
        u32 ah1 = pack_h2(f1.x, f1.y);
        u32 ah2 = pack_h2(f2.x, f2.y);
        u32 ah3 = pack_h2(f3.x, f3.y);
        #pragma unroll
        for (int n = 0; n < 8; n++) {
            int nb = n * 8 + grp;
            u32 b0r = *(const u32*)&Bb[nb * KPAD + k0 + 2 * tig];
            u32 b1r = *(const u32*)&Bb[nb * KPAD + k0 + 2 * tig + 8];
            mma_f16(aB[n], ah0, ah1, ah2, ah3, b0r, b1r);
            u32 g0r = *(const u32*)&Bg[nb * KPAD + k0 + 2 * tig];
            u32 g1r = *(const u32*)&Bg[nb * KPAD + k0 + 2 * tig + 8];
            mma_f16(aG[n], ah0, ah1, ah2, ah3, g0r, g1r);
        }
    }

    int r0 = i0 + m0 + grp;
    int r1 = r0 + 8;
    #pragma unroll
    for (int n = 0; n < 8; n++) {
        int gene = g0 + n * 8 + tig * 2;
        if (gene >= NG) continue;
        float2 bb = *(const float2*)&b1[gene];
        float2 bg = *(const float2*)&b1[NG + gene];
        if (r0 < NN) {
            float2 u = *(const float2*)&xu[(size_t)r0 * NG + gene];
            float2 s = *(const float2*)&xs[(size_t)r0 * NG + gene];
            float2 o;
            o.x = (aB[n][0] + bb.x) * u.x + (aG[n][0] + bg.x) * s.x;
            o.y = (aB[n][1] + bb.y) * u.y + (aG[n][1] + bg.y) * s.y;
            *(float2*)&out[(size_t)r0 * NG + gene] = o;
        }
        if (r1 < NN) {
            float2 u = *(const float2*)&xu[(size_t)r1 * NG + gene];
            float2 s = *(const float2*)&xs[(size_t)r1 * NG + gene];
            float2 o;
            o.x = (aB[n][2] + bb.x) * u.x + (aG[n][2] + bg.x) * s.x;
            o.y = (aB[n][3] + bb.y) * u.y + (aG[n][3] + bg.y) * s.y;
            *(float2*)&out[(size_t)r1 * NG + gene] = o;
        }
    }
}

// ---------------- host launcher ---------------------------------------------------
extern "C" void kernel_launch(void* const* d_in, const int* in_sizes, int n_in,
                              void* d_out, int out_size) {
    const float* xu = (const float*)d_in[0];
    const float* xs = (const float*)d_in[1];
    const float* W0 = (const float*)d_in[2];
    const float* b0 = (const float*)d_in[3];
    const float* W1 = (const float*)d_in[4];
    const float* b1 = (const float*)d_in[5];
    const int* src = (const int*)d_in[6];
    const int* dst = (const int*)d_in[7];
    int E = in_sizes[6];
    float* out = (float*)d_out;

    void *p_degi, *p_dego, *p_ctr, *p_t, *p_hs, *p_z;
    cudaGetSymbolAddress(&p_degi, g_deg_in);
    cudaGetSymbolAddress(&p_dego, g_deg_out);
    cudaGetSymbolAddress(&p_ctr, g_ctr);
    cudaGetSymbolAddress(&p_t, g_t);
    cudaGetSymbolAddress(&p_hs, g_hs);
    cudaGetSymbolAddress(&p_z, g_z);

    static cudaStream_t s1 = nullptr;
    static cudaEvent_t evFork = nullptr, evJoin = nullptr;
    static int attr_done = 0;
    if (!attr_done) {
        cudaFuncSetAttribute(k_gemm1, cudaFuncAttributeMaxDynamicSharedMemorySize, G1_SMEM);
        cudaFuncSetAttribute(k_out, cudaFuncAttributeMaxDynamicSharedMemorySize, KO_SMEM);
        cudaStreamCreateWithFlags(&s1, cudaStreamNonBlocking);
        cudaEventCreateWithFlags(&evFork, cudaEventDisableTiming);
        cudaEventCreateWithFlags(&evJoin, cudaEventDisableTiming);
        attr_done = 1;
    }

    cudaEventRecord(evFork, 0);
    cudaStreamWaitEvent(s1, evFork, 0);

    // chain B: CSR build
    cudaMemsetAsync(p_degi, 0, NN * sizeof(int), s1);
    cudaMemsetAsync(p_dego, 0, NN * sizeof(int), s1);
    cudaMemsetAsync(p_ctr, 0, NN * sizeof(int), s1);
    k_count<<<(E / 4 + 255) / 256, 256, 0, s1>>>(src, dst, E);
    k_scan1<<<NB, 1024, 0, s1>>>();
    k_scan2<<<1, 64, 0, s1>>>();
    k_scan3<<<NB, 1024, 0, s1>>>();
    k_fill<<<(E / 4 + 255) / 256, 256, 0, s1>>>(src, dst, E);
    cudaEventRecord(evJoin, s1);

    // chain A: weights + GEMM1
    k_prep<<<(HID * KW + 255) / 256, 256>>>(W0, W1);
    k_gemm1<<<(NN + 127) / 128, 256, G1_SMEM>>>(xu, xs);

    cudaStreamWaitEvent(0, evJoin, 0);

    k_gather<0><<<(NN * 32 + 255) / 256, 256>>>((const __half*)p_t, b0, p_hs);
    k_gather<1><<<(NN * 32 + 255) / 256, 256>>>((const __half*)p_hs, b0, p_z);
    k_out<<<dim3(16, (NN + 127) / 128), 256, KO_SMEM>>>(xu, xs, b1, out);
}